// round 6
// baseline (speedup 1.0000x reference)
#include <cuda_runtime.h>

#define Bb 8
#define Nn 2048
#define CIN 128
#define Ff 64
#define ALPHA 0.01f
#define TI 16
#define TJ 16
#define JS 8                         // j-dimension splits
#define JT_PER_SPLIT (Nn / TJ / JS)  // 16

__device__ float g_h[Bb * Nn * Ff];             // 4 MB
__device__ float g_s1[Bb * Nn];
__device__ float g_s2[Bb * Nn];
__device__ float g_c1[Bb];
__device__ float g_c2[Bb];
__device__ float g_e1[Bb * Nn];                 // exp(s1-c1)*A   (pos branch, i side)
__device__ float g_f1[Bb * Nn];                 // exp(a(s1-c1))*B (neg branch, i side)
__device__ float4 g_sef[Bb * Nn];               // (s2, exp(s2-c2), exp(a(s2-c2)), 0)
__device__ float g_part[JS * Bb * Nn * Ff];     // 33.5 MB partial weighted sums
__device__ float g_psum[JS * Bb * Nn];          // partial softmax denominators

__device__ __forceinline__ unsigned long long ffma2(unsigned long long a,
                                                    unsigned long long b,
                                                    unsigned long long c) {
    unsigned long long d;
    asm("fma.rn.f32x2 %0, %1, %2, %3;" : "=l"(d) : "l"(a), "l"(b), "l"(c));
    return d;
}

// ---------------------------------------------------------------------------
// Kernel 1: h = inp @ W   ([16384,128] @ [128,64])
// ---------------------------------------------------------------------------
__global__ __launch_bounds__(256) void k_h(const float* __restrict__ inp,
                                           const float* __restrict__ W) {
    __shared__ float Ws[CIN * Ff];
    __shared__ float Is[TI * CIN];
    const int tid  = threadIdx.x;
    const int row0 = blockIdx.x * TI;

    for (int i = tid; i < CIN * Ff; i += 256) Ws[i] = W[i];
    for (int i = tid; i < TI * CIN; i += 256) Is[i] = inp[row0 * CIN + i];
    __syncthreads();

    const int col = tid & 63;
    const int r0  = tid >> 6;
    float acc[4] = {0.f, 0.f, 0.f, 0.f};
    #pragma unroll 4
    for (int c = 0; c < CIN; c++) {
        const float wv = Ws[c * Ff + col];
        #pragma unroll
        for (int k = 0; k < 4; k++)
            acc[k] += Is[(r0 + 4 * k) * CIN + c] * wv;
    }
    #pragma unroll
    for (int k = 0; k < 4; k++)
        g_h[(row0 + r0 + 4 * k) * Ff + col] = acc[k];
}

// ---------------------------------------------------------------------------
// Kernel 2: s1 = h @ a1, s2 = h @ a2   (one warp per row)
// ---------------------------------------------------------------------------
__global__ __launch_bounds__(256) void k_s(const float* __restrict__ a) {
    const int warp = threadIdx.x >> 5;
    const int lane = threadIdx.x & 31;
    const int row  = blockIdx.x * 8 + warp;

    const float2 hv = ((const float2*)(g_h + row * Ff))[lane];
    const float a1l = a[2 * lane],       a1h = a[2 * lane + 1];
    const float a2l = a[Ff + 2 * lane],  a2h = a[Ff + 2 * lane + 1];
    float p1 = hv.x * a1l + hv.y * a1h;
    float p2 = hv.x * a2l + hv.y * a2h;
    #pragma unroll
    for (int o = 16; o; o >>= 1) {
        p1 += __shfl_xor_sync(0xFFFFFFFFu, p1, o);
        p2 += __shfl_xor_sync(0xFFFFFFFFu, p2, o);
    }
    if (lane == 0) {
        g_s1[row] = p1;
        g_s2[row] = p2;
    }
}

// ---------------------------------------------------------------------------
// Kernel 3: per-batch maxima of s1 and s2
// ---------------------------------------------------------------------------
__global__ __launch_bounds__(256) void k_gmax() {
    __shared__ float r1[256], r2[256];
    const int b = blockIdx.x, tid = threadIdx.x;
    float m1 = -3.0e38f, m2 = -3.0e38f;
    for (int j = tid; j < Nn; j += 256) {
        m1 = fmaxf(m1, g_s1[b * Nn + j]);
        m2 = fmaxf(m2, g_s2[b * Nn + j]);
    }
    r1[tid] = m1; r2[tid] = m2;
    __syncthreads();
    #pragma unroll
    for (int s = 128; s > 0; s >>= 1) {
        if (tid < s) {
            r1[tid] = fmaxf(r1[tid], r1[tid + s]);
            r2[tid] = fmaxf(r2[tid], r2[tid + s]);
        }
        __syncthreads();
    }
    if (tid == 0) { g_c1[b] = r1[0]; g_c2[b] = r2[0]; }
}

// ---------------------------------------------------------------------------
// Kernel 3b: factorized softmax terms (4 exps per node instead of N per node).
//   x>0: w = e1*e2 = exp(x - S);  x<=0: w = f1*f2 = exp(a*x - S); same shift S.
// ---------------------------------------------------------------------------
__global__ __launch_bounds__(256) void k_factors() {
    const int idx = blockIdx.x * 256 + threadIdx.x;   // [0, 16384)
    const int b   = idx >> 11;
    const float c1 = g_c1[b], c2 = g_c2[b];
    const float C  = c1 + c2;
    const float S  = C > 0.f ? C : ALPHA * C;         // lrelu(C) >= lrelu(x) ∀x
    const float A  = __expf(C - S);                   // <= 1
    const float Bf = __expf(ALPHA * C - S);           // <= 1
    const float s1 = g_s1[idx];
    const float s2 = g_s2[idx];
    g_e1[idx] = __expf(s1 - c1) * A;
    g_f1[idx] = __expf(ALPHA * (s1 - c1)) * Bf;
    const float e2 = __expf(s2 - c2);
    const float f2 = __expf(ALPHA * (s2 - c2));
    g_sef[idx] = make_float4(s2, e2, f2, 0.f);
}

// ---------------------------------------------------------------------------
// Kernel 4: fused mask + factored-weight + partial PV accumulation.
// warp = batch. Lane owns f-columns {lane, lane+32} for all 16 i rows.
// Phase 1: w[i][jj] via 2 FSEL + FMUL (no exp). Phase 2: rank-16 outer product,
// w as broadcast LDS.128 (pre-packed f32x2), h as 2 distinct LDS.32.
// ---------------------------------------------------------------------------
__global__ __launch_bounds__(256, 3) void k_attn(const float* __restrict__ adj) {
    __shared__ __align__(16) float hs[Bb * TJ * Ff];   // 32 KB  [b][jj][f]
    __shared__ float adjs[TJ][TI + 1];                 // transposed adj tile
    __shared__ __align__(16) float4 sefs[Bb][TJ];      // 2 KB (s2,e2,f2,0)
    __shared__ __align__(16) float wsm[Bb][TJ][TI];    // 8 KB warp-private w

    const int tid   = threadIdx.x;
    const int b     = tid >> 5;            // warp id = batch
    const int lane  = tid & 31;
    const int il    = lane & 15;           // phase-1 i row
    const int jjo   = lane >> 4;           // phase-1 jj parity
    const int i0    = blockIdx.x * TI;
    const int split = blockIdx.y;
    const int ig1   = i0 + il;

    const int a_ii = tid >> 4;
    const int a_jj = tid & 15;

    const float s1v = g_s1[b * Nn + ig1];
    const float e1v = g_e1[b * Nn + ig1];
    const float f1v = g_f1[b * Nn + ig1];

    unsigned long long acc[2][8];          // [fgroup][ipair] f32x2 over i
    #pragma unroll
    for (int g = 0; g < 2; g++)
        #pragma unroll
        for (int p = 0; p < 8; p++) acc[g][p] = 0ull;
    float sumw = 0.0f;

    const int jt0 = split * JT_PER_SPLIT;
    for (int jt = jt0; jt < jt0 + JT_PER_SPLIT; jt++) {
        const int j0 = jt * TJ;
        __syncthreads();
        adjs[a_jj][a_ii] = adj[(i0 + a_ii) * Nn + j0 + a_jj];
        if (tid < Bb * TJ)
            sefs[tid >> 4][tid & 15] = g_sef[(tid >> 4) * Nn + j0 + (tid & 15)];
        #pragma unroll
        for (int r = 0; r < 8; r++) {
            const int idx = r * 256 + tid;
            const int row = idx >> 4;              // b*16 + jj
            const int f4  = idx & 15;
            const int bb  = row >> 4, jj = row & 15;
            const float4 v =
                *(const float4*)&g_h[(bb * Nn + j0 + jj) * Ff + f4 * 4];
            *(float4*)&hs[row * Ff + f4 * 4] = v;
        }
        __syncthreads();

        // ---- phase 1: factored weights, no exp ----
        #pragma unroll
        for (int u = 0; u < 8; u++) {
            const int jj = 2 * u + jjo;
            const float av  = adjs[jj][il];
            const float4 sv = sefs[b][jj];         // broadcast LDS.128
            const float x   = s1v + sv.x;
            const bool pos  = x > 0.0f;
            const float gi  = pos ? e1v : f1v;
            const float qj  = pos ? sv.y : sv.z;
            float w = gi * qj;                     // = exp(lrelu(x) - S)
            const bool m = (av > 0.0f) || (j0 + jj == ig1);
            w = m ? w : 0.0f;
            sumw += w;
            wsm[b][jj][il] = w;
        }
        __syncwarp();

        // ---- phase 2: rank-16 outer-product update ----
        #pragma unroll
        for (int jj = 0; jj < TJ; jj++) {
            const float h0 = hs[(b * TJ + jj) * Ff + lane];
            const float h1 = hs[(b * TJ + jj) * Ff + lane + 32];
            unsigned long long hh0, hh1;
            asm("mov.b64 %0, {%1, %1};" : "=l"(hh0) : "f"(h0));
            asm("mov.b64 %0, {%1, %1};" : "=l"(hh1) : "f"(h1));
            const ulonglong2* wp = (const ulonglong2*)&wsm[b][jj][0];
            #pragma unroll
            for (int q = 0; q < 4; q++) {
                const ulonglong2 wv = wp[q];      // broadcast LDS.128
                acc[0][2 * q]     = ffma2(wv.x, hh0, acc[0][2 * q]);
                acc[1][2 * q]     = ffma2(wv.x, hh1, acc[1][2 * q]);
                acc[0][2 * q + 1] = ffma2(wv.y, hh0, acc[0][2 * q + 1]);
                acc[1][2 * q + 1] = ffma2(wv.y, hh1, acc[1][2 * q + 1]);
            }
        }
        __syncwarp();
    }

    // ---- epilogue: write partials ----
    float* base = &g_part[((split * Bb + b) * Nn + i0) * Ff];
    #pragma unroll
    for (int p = 0; p < 8; p++) {
        #pragma unroll
        for (int g = 0; g < 2; g++) {
            const unsigned long long v = acc[g][p];
            const float lo = __uint_as_float((unsigned)(v & 0xFFFFFFFFull));
            const float hi = __uint_as_float((unsigned)(v >> 32));
            base[(2 * p)     * Ff + lane + 32 * g] = lo;
            base[(2 * p + 1) * Ff + lane + 32 * g] = hi;
        }
    }
    sumw += __shfl_xor_sync(0xFFFFFFFFu, sumw, 16);
    if (lane < 16)
        g_psum[(split * Bb + b) * Nn + i0 + lane] = sumw;
}

// ---------------------------------------------------------------------------
// Kernel 5: reduce splits + normalize. block = 256 threads = 4 rows x 64 f.
// ---------------------------------------------------------------------------
__global__ __launch_bounds__(256) void k_norm(float* __restrict__ out) {
    const int tid = threadIdx.x;
    const int row = blockIdx.x * 4 + (tid >> 6);   // (b*Nn + i)
    const int f   = tid & 63;

    float den = 0.0f;
    #pragma unroll
    for (int s = 0; s < JS; s++) den += g_psum[s * Bb * Nn + row];

    float num = 0.0f;
    #pragma unroll
    for (int s = 0; s < JS; s++)
        num += g_part[(s * Bb * Nn + row) * Ff + f];

    out[row * Ff + f] = num / den;
}

// ---------------------------------------------------------------------------
extern "C" void kernel_launch(void* const* d_in, const int* in_sizes, int n_in,
                              void* d_out, int out_size) {
    const float* inp = (const float*)d_in[0];   // [8,2048,128]
    const float* adj = (const float*)d_in[1];   // [2048,2048]
    const float* W   = (const float*)d_in[2];   // [128,64]
    const float* a   = (const float*)d_in[3];   // [128,1]
    float* out = (float*)d_out;                 // [8,2048,64]

    k_h      <<<(Bb * Nn) / TI, 256>>>(inp, W);
    k_s      <<<(Bb * Nn) / 8, 256>>>(a);
    k_gmax   <<<Bb, 256>>>();
    k_factors<<<(Bb * Nn) / 256, 256>>>();
    dim3 grid_attn(Nn / TI, JS);
    k_attn<<<grid_attn, 256>>>(adj);
    k_norm<<<(Bb * Nn) / 4, 256>>>(out);
}

// round 7
// speedup vs baseline: 1.1595x; 1.1595x over previous
#include <cuda_runtime.h>

#define Bb 8
#define Nn 2048
#define CIN 128
#define Ff 64
#define ALPHA 0.01f
#define TI 16
#define TJ 16
#define JS 8                         // j-dimension splits
#define JT_PER_SPLIT (Nn / TJ / JS)  // 16

__device__ float g_h[Bb * Nn * Ff];             // 4 MB
__device__ float g_s1[Bb * Nn];
__device__ float g_s2[Bb * Nn];
__device__ float g_c1[Bb];
__device__ float g_c2[Bb];
__device__ float g_e1[Bb * Nn];                 // exp(s1-c1)*A   (pos branch, i side)
__device__ float g_f1[Bb * Nn];                 // exp(a(s1-c1))*B (neg branch, i side)
__device__ float4 g_sef[Bb * Nn];               // (s2, exp(s2-c2), exp(a(s2-c2)), 0)
__device__ float g_part[JS * Bb * Nn * Ff];     // 33.5 MB partial weighted sums
__device__ float g_psum[JS * Bb * Nn];          // partial softmax denominators

__device__ __forceinline__ unsigned long long ffma2(unsigned long long a,
                                                    unsigned long long b,
                                                    unsigned long long c) {
    unsigned long long d;
    asm("fma.rn.f32x2 %0, %1, %2, %3;" : "=l"(d) : "l"(a), "l"(b), "l"(c));
    return d;
}

// ---------------------------------------------------------------------------
// Kernel 1: h = inp @ W   ([16384,128] @ [128,64])
// ---------------------------------------------------------------------------
__global__ __launch_bounds__(256) void k_h(const float* __restrict__ inp,
                                           const float* __restrict__ W) {
    __shared__ float Ws[CIN * Ff];
    __shared__ float Is[TI * CIN];
    const int tid  = threadIdx.x;
    const int row0 = blockIdx.x * TI;

    for (int i = tid; i < CIN * Ff; i += 256) Ws[i] = W[i];
    for (int i = tid; i < TI * CIN; i += 256) Is[i] = inp[row0 * CIN + i];
    __syncthreads();

    const int col = tid & 63;
    const int r0  = tid >> 6;
    float acc[4] = {0.f, 0.f, 0.f, 0.f};
    #pragma unroll 4
    for (int c = 0; c < CIN; c++) {
        const float wv = Ws[c * Ff + col];
        #pragma unroll
        for (int k = 0; k < 4; k++)
            acc[k] += Is[(r0 + 4 * k) * CIN + c] * wv;
    }
    #pragma unroll
    for (int k = 0; k < 4; k++)
        g_h[(row0 + r0 + 4 * k) * Ff + col] = acc[k];
}

// ---------------------------------------------------------------------------
// Kernel 2: s1 = h @ a1, s2 = h @ a2   (one warp per row)
// ---------------------------------------------------------------------------
__global__ __launch_bounds__(256) void k_s(const float* __restrict__ a) {
    const int warp = threadIdx.x >> 5;
    const int lane = threadIdx.x & 31;
    const int row  = blockIdx.x * 8 + warp;

    const float2 hv = ((const float2*)(g_h + row * Ff))[lane];
    const float a1l = a[2 * lane],       a1h = a[2 * lane + 1];
    const float a2l = a[Ff + 2 * lane],  a2h = a[Ff + 2 * lane + 1];
    float p1 = hv.x * a1l + hv.y * a1h;
    float p2 = hv.x * a2l + hv.y * a2h;
    #pragma unroll
    for (int o = 16; o; o >>= 1) {
        p1 += __shfl_xor_sync(0xFFFFFFFFu, p1, o);
        p2 += __shfl_xor_sync(0xFFFFFFFFu, p2, o);
    }
    if (lane == 0) {
        g_s1[row] = p1;
        g_s2[row] = p2;
    }
}

// ---------------------------------------------------------------------------
// Kernel 3: per-batch maxima of s1 and s2
// ---------------------------------------------------------------------------
__global__ __launch_bounds__(256) void k_gmax() {
    __shared__ float r1[256], r2[256];
    const int b = blockIdx.x, tid = threadIdx.x;
    float m1 = -3.0e38f, m2 = -3.0e38f;
    for (int j = tid; j < Nn; j += 256) {
        m1 = fmaxf(m1, g_s1[b * Nn + j]);
        m2 = fmaxf(m2, g_s2[b * Nn + j]);
    }
    r1[tid] = m1; r2[tid] = m2;
    __syncthreads();
    #pragma unroll
    for (int s = 128; s > 0; s >>= 1) {
        if (tid < s) {
            r1[tid] = fmaxf(r1[tid], r1[tid + s]);
            r2[tid] = fmaxf(r2[tid], r2[tid + s]);
        }
        __syncthreads();
    }
    if (tid == 0) { g_c1[b] = r1[0]; g_c2[b] = r2[0]; }
}

// ---------------------------------------------------------------------------
// Kernel 3b: factorized softmax terms.
//   x>0: w = e1*e2 = exp(x - S);  x<=0: w = f1*f2 = exp(a*x - S); same shift S.
// ---------------------------------------------------------------------------
__global__ __launch_bounds__(256) void k_factors() {
    const int idx = blockIdx.x * 256 + threadIdx.x;   // [0, 16384)
    const int b   = idx >> 11;
    const float c1 = g_c1[b], c2 = g_c2[b];
    const float C  = c1 + c2;
    const float S  = C > 0.f ? C : ALPHA * C;         // lrelu(C) >= lrelu(x) ∀x
    const float A  = __expf(C - S);                   // <= 1
    const float Bf = __expf(ALPHA * C - S);           // <= 1
    const float s1 = g_s1[idx];
    const float s2 = g_s2[idx];
    g_e1[idx] = __expf(s1 - c1) * A;
    g_f1[idx] = __expf(ALPHA * (s1 - c1)) * Bf;
    const float e2 = __expf(s2 - c2);
    const float f2 = __expf(ALPHA * (s2 - c2));
    g_sef[idx] = make_float4(s2, e2, f2, 0.f);
}

// ---------------------------------------------------------------------------
// Kernel 4: fused mask + factored-weight + partial PV accumulation.
// warp = batch; lane owns f-columns {lane, lane+32} for all 16 i rows.
// h: direct coalesced LDG into registers (no smem round-trip).
// adj/sef: double-buffered smem via register prefetch, 1 barrier per tile.
// ---------------------------------------------------------------------------
__global__ __launch_bounds__(256, 3) void k_attn(const float* __restrict__ adj) {
    __shared__ float adjs[2][TJ][TI + 1];              // [buf][jj][i]
    __shared__ __align__(16) float4 sefs[2][Bb][TJ];   // [buf][b][jj]
    __shared__ __align__(16) float wsm[Bb][TJ][TI];    // 8 KB warp-private w

    const int tid   = threadIdx.x;
    const int b     = tid >> 5;            // warp id = batch
    const int lane  = tid & 31;
    const int il    = lane & 15;           // phase-1 i row
    const int jjo   = lane >> 4;           // phase-1 jj parity
    const int i0    = blockIdx.x * TI;
    const int split = blockIdx.y;
    const int ig1   = i0 + il;

    const int a_ii = tid >> 4;             // adj loader: row
    const int a_jj = tid & 15;             // adj loader: col

    const float s1v = g_s1[b * Nn + ig1];
    const float e1v = g_e1[b * Nn + ig1];
    const float f1v = g_f1[b * Nn + ig1];

    unsigned long long acc[2][8];          // [fgroup][ipair] f32x2 over i
    #pragma unroll
    for (int g = 0; g < 2; g++)
        #pragma unroll
        for (int p = 0; p < 8; p++) acc[g][p] = 0ull;
    float sumw = 0.0f;

    const int jt0 = split * JT_PER_SPLIT;
    const int j00 = jt0 * TJ;

    // preload tile 0
    adjs[0][a_jj][a_ii] = adj[(i0 + a_ii) * Nn + j00 + a_jj];
    if (tid < Bb * TJ)
        sefs[0][tid >> 4][tid & 15] = g_sef[(tid >> 4) * Nn + j00 + (tid & 15)];
    __syncthreads();

    for (int t = 0; t < JT_PER_SPLIT; t++) {
        const int j0  = j00 + t * TJ;
        const int buf = t & 1;
        const bool last = (t == JT_PER_SPLIT - 1);

        // prefetch next adj/sef tile into registers (latency hidden by compute)
        float pa = 0.0f;
        float4 ps = make_float4(0.f, 0.f, 0.f, 0.f);
        if (!last) {
            pa = adj[(i0 + a_ii) * Nn + j0 + TJ + a_jj];
            if (tid < Bb * TJ)
                ps = g_sef[(tid >> 4) * Nn + j0 + TJ + (tid & 15)];
        }

        // h for this tile: coalesced LDG.32 into registers (issued early)
        float hreg[2][TJ];
        const float* hb = &g_h[(b * Nn + j0) * Ff + lane];
        #pragma unroll
        for (int jj = 0; jj < TJ; jj++) {
            hreg[0][jj] = hb[jj * Ff];
            hreg[1][jj] = hb[jj * Ff + 32];
        }

        // ---- phase 1: factored weights, no exp ----
        #pragma unroll
        for (int u = 0; u < 8; u++) {
            const int jj = 2 * u + jjo;
            const float av  = adjs[buf][jj][il];
            const float4 sv = sefs[buf][b][jj];    // broadcast LDS.128
            const float x   = s1v + sv.x;
            const bool pos  = x > 0.0f;
            const float gi  = pos ? e1v : f1v;
            const float qj  = pos ? sv.y : sv.z;
            float w = gi * qj;                     // = exp(lrelu(x) - S)
            const bool m = (av > 0.0f) || (j0 + jj == ig1);
            w = m ? w : 0.0f;
            sumw += w;
            wsm[b][jj][il] = w;
        }
        __syncwarp();

        // ---- phase 2: rank-16 outer-product update ----
        #pragma unroll
        for (int jj = 0; jj < TJ; jj++) {
            unsigned long long hh0, hh1;
            asm("mov.b64 %0, {%1, %1};" : "=l"(hh0) : "f"(hreg[0][jj]));
            asm("mov.b64 %0, {%1, %1};" : "=l"(hh1) : "f"(hreg[1][jj]));
            const ulonglong2* wp = (const ulonglong2*)&wsm[b][jj][0];
            #pragma unroll
            for (int q = 0; q < 4; q++) {
                const ulonglong2 wv = wp[q];      // broadcast LDS.128
                acc[0][2 * q]     = ffma2(wv.x, hh0, acc[0][2 * q]);
                acc[1][2 * q]     = ffma2(wv.x, hh1, acc[1][2 * q]);
                acc[0][2 * q + 1] = ffma2(wv.y, hh0, acc[0][2 * q + 1]);
                acc[1][2 * q + 1] = ffma2(wv.y, hh1, acc[1][2 * q + 1]);
            }
        }
        __syncwarp();

        // commit prefetched tile to the other buffer
        if (!last) {
            adjs[buf ^ 1][a_jj][a_ii] = pa;
            if (tid < Bb * TJ)
                sefs[buf ^ 1][tid >> 4][tid & 15] = ps;
        }
        __syncthreads();
    }

    // ---- epilogue: write partials ----
    float* base = &g_part[((split * Bb + b) * Nn + i0) * Ff];
    #pragma unroll
    for (int p = 0; p < 8; p++) {
        #pragma unroll
        for (int g = 0; g < 2; g++) {
            const unsigned long long v = acc[g][p];
            const float lo = __uint_as_float((unsigned)(v & 0xFFFFFFFFull));
            const float hi = __uint_as_float((unsigned)(v >> 32));
            base[(2 * p)     * Ff + lane + 32 * g] = lo;
            base[(2 * p + 1) * Ff + lane + 32 * g] = hi;
        }
    }
    sumw += __shfl_xor_sync(0xFFFFFFFFu, sumw, 16);
    if (lane < 16)
        g_psum[(split * Bb + b) * Nn + i0 + lane] = sumw;
}

// ---------------------------------------------------------------------------
// Kernel 5: reduce splits + normalize. block = 256 threads = 4 rows x 64 f.
// ---------------------------------------------------------------------------
__global__ __launch_bounds__(256) void k_norm(float* __restrict__ out) {
    const int tid = threadIdx.x;
    const int row = blockIdx.x * 4 + (tid >> 6);   // (b*Nn + i)
    const int f   = tid & 63;

    float den = 0.0f;
    #pragma unroll
    for (int s = 0; s < JS; s++) den += g_psum[s * Bb * Nn + row];

    float num = 0.0f;
    #pragma unroll
    for (int s = 0; s < JS; s++)
        num += g_part[(s * Bb * Nn + row) * Ff + f];

    out[row * Ff + f] = num / den;
}

// ---------------------------------------------------------------------------
extern "C" void kernel_launch(void* const* d_in, const int* in_sizes, int n_in,
                              void* d_out, int out_size) {
    const float* inp = (const float*)d_in[0];   // [8,2048,128]
    const float* adj = (const float*)d_in[1];   // [2048,2048]
    const float* W   = (const float*)d_in[2];   // [128,64]
    const float* a   = (const float*)d_in[3];   // [128,1]
    float* out = (float*)d_out;                 // [8,2048,64]

    k_h      <<<(Bb * Nn) / TI, 256>>>(inp, W);
    k_s      <<<(Bb * Nn) / 8, 256>>>(a);
    k_gmax   <<<Bb, 256>>>();
    k_factors<<<(Bb * Nn) / 256, 256>>>();
    dim3 grid_attn(Nn / TI, JS);
    k_attn<<<grid_attn, 256>>>(adj);
    k_norm<<<(Bb * Nn) / 4, 256>>>(out);
}